// round 8
// baseline (speedup 1.0000x reference)
#include <cuda_runtime.h>

// AttentionAggregator: out[n] = sum_k softmax_k(feats[n,k]·w) * feats[n,k],
// feats[n,k] = embed_table[neigh_idx[n,k]].
// table [VOCAB,128] f32, attn_w [128] f32, neigh_idx [N,10] (int32 or int64), out [N,128] f32.
//
// R8 = R6 compute body (warp-per-node, online softmax in 2 groups of 5,
//      inline dtype detect, __stcs output) restructured as a PERSISTENT grid:
//      912 blocks, grid-stride over nodes, next node's indices prefetched
//      during the current node's compute. Removes ~14 waves of block
//      launch/retire + wave-transition overhead; we sit at the LTS ceiling
//      (~571 MB / ~11 TB/s), so scheduling overhead is all that's left.

#define K_NEIGH 10
#define GROUP 5
#define WARPS_PER_BLOCK 8

__global__ __launch_bounds__(256, 6) void attn_agg_kernel(
    const float* __restrict__ table,
    const float* __restrict__ attn_w,
    const int*   __restrict__ idx_words,   // raw index buffer viewed as int32 words
    float* __restrict__ out,
    int n_nodes,
    int vocab)
{
    int warp = threadIdx.x >> 5;
    int lane = threadIdx.x & 31;
    int node = blockIdx.x * WARPS_PER_BLOCK + warp;
    int stride = gridDim.x * WARPS_PER_BLOCK;
    if (node >= n_nodes) return;

    // Inline dtype detection (once per warp): int64 indices in [0,2^31) have
    // all-zero odd int32 words; an int32 buffer has random vocab ids there.
    int oddw = 0;
    if (lane < 16) oddw = idx_words[2 * lane + 1];
    bool is32 = __ballot_sync(0xffffffffu, oddw != 0) != 0u;

    float4 w4 = ((const float4*)attn_w)[lane];

    // First node's indices (lanes 0..9 -> row byte offsets).
    unsigned mybase = 0;
    if (lane < K_NEIGH) {
        int r;
        if (is32) r = idx_words[node * K_NEIGH + lane];
        else      r = (int)((const long long*)idx_words)[(size_t)node * K_NEIGH + lane];
        r = min(max(r, 0), vocab - 1);
        mybase = (unsigned)r * 512u;
    }

    while (true) {
        // Prefetch next node's indices: issued before this node's compute so
        // the idx-load latency is hidden behind ~1.5k cycles of gather+math.
        int nnext = node + stride;
        unsigned nextbase = 0;
        if (nnext < n_nodes && lane < K_NEIGH) {
            int r;
            if (is32) r = idx_words[nnext * K_NEIGH + lane];
            else      r = (int)((const long long*)idx_words)[(size_t)nnext * K_NEIGH + lane];
            r = min(max(r, 0), vocab - 1);
            nextbase = (unsigned)r * 512u;
        }

        float4 f[GROUP];
        float  s[GROUP];

        // ---- Group A: neighbors 0..4 ----
        #pragma unroll
        for (int k = 0; k < GROUP; k++) {
            unsigned off = __shfl_sync(0xffffffffu, mybase, k) + (unsigned)(lane * 16);
            f[k] = *(const float4*)((const char*)table + off);
            s[k] = f[k].x * w4.x + f[k].y * w4.y + f[k].z * w4.z + f[k].w * w4.w;
        }
        #pragma unroll
        for (int off = 16; off > 0; off >>= 1) {
            #pragma unroll
            for (int k = 0; k < GROUP; k++)
                s[k] += __shfl_xor_sync(0xffffffffu, s[k], off);
        }
        float m = s[0];
        #pragma unroll
        for (int k = 1; k < GROUP; k++) m = fmaxf(m, s[k]);
        float d = 0.0f;
        float4 acc = make_float4(0.f, 0.f, 0.f, 0.f);
        #pragma unroll
        for (int k = 0; k < GROUP; k++) {
            float e = __expf(s[k] - m);
            d += e;
            acc.x = fmaf(e, f[k].x, acc.x);
            acc.y = fmaf(e, f[k].y, acc.y);
            acc.z = fmaf(e, f[k].z, acc.z);
            acc.w = fmaf(e, f[k].w, acc.w);
        }

        // ---- Group B: neighbors 5..9 (reuse f/s registers) ----
        #pragma unroll
        for (int k = 0; k < GROUP; k++) {
            unsigned off = __shfl_sync(0xffffffffu, mybase, GROUP + k) + (unsigned)(lane * 16);
            f[k] = *(const float4*)((const char*)table + off);
            s[k] = f[k].x * w4.x + f[k].y * w4.y + f[k].z * w4.z + f[k].w * w4.w;
        }
        #pragma unroll
        for (int off = 16; off > 0; off >>= 1) {
            #pragma unroll
            for (int k = 0; k < GROUP; k++)
                s[k] += __shfl_xor_sync(0xffffffffu, s[k], off);
        }
        float mB = s[0];
        #pragma unroll
        for (int k = 1; k < GROUP; k++) mB = fmaxf(mB, s[k]);

        // Online-softmax rescale to the combined max.
        float newm  = fmaxf(m, mB);
        float scale = __expf(m - newm);
        d *= scale;
        acc.x *= scale; acc.y *= scale; acc.z *= scale; acc.w *= scale;

        #pragma unroll
        for (int k = 0; k < GROUP; k++) {
            float e = __expf(s[k] - newm);
            d += e;
            acc.x = fmaf(e, f[k].x, acc.x);
            acc.y = fmaf(e, f[k].y, acc.y);
            acc.z = fmaf(e, f[k].z, acc.z);
            acc.w = fmaf(e, f[k].w, acc.w);
        }

        float inv = __frcp_rn(d);
        acc.x *= inv; acc.y *= inv; acc.z *= inv; acc.w *= inv;

        // Streaming store: keep the 51MB output from evicting the table in L2.
        __stcs(&((float4*)out)[(size_t)node * 32 + lane], acc);

        if (nnext >= n_nodes) break;
        node   = nnext;
        mybase = nextbase;
    }
}

extern "C" void kernel_launch(void* const* d_in, const int* in_sizes, int n_in,
                              void* d_out, int out_size)
{
    // Identify inputs by element count:
    //   attn_w: exactly 128; table: large multiple of 128; idx: the remaining one.
    int ti = -1, wi = -1, ii = -1;
    for (int i = 0; i < n_in; i++) {
        if (in_sizes[i] == 128 && wi < 0) { wi = i; continue; }
        if (in_sizes[i] >= (1 << 20) && (in_sizes[i] % 128) == 0 && ti < 0) { ti = i; continue; }
    }
    for (int i = 0; i < n_in; i++) if (i != ti && i != wi) { ii = i; break; }

    const float* table  = (const float*)d_in[ti];
    const float* attn_w = (const float*)d_in[wi];
    const int*   nidx   = (const int*)d_in[ii];

    int n_nodes = in_sizes[ii] / K_NEIGH;
    int vocab   = in_sizes[ti] / 128;

    // Persistent grid: 152 SMs x 6 blocks/SM; grid-stride covers all nodes.
    int blocks_needed = (n_nodes + WARPS_PER_BLOCK - 1) / WARPS_PER_BLOCK;
    int blocks = 152 * 6;
    if (blocks > blocks_needed) blocks = blocks_needed;

    attn_agg_kernel<<<blocks, 256>>>(table, attn_w, nidx, (float*)d_out,
                                     n_nodes, vocab);
}

// round 9
// speedup vs baseline: 1.1737x; 1.1737x over previous
#include <cuda_runtime.h>

// AttentionAggregator: out[n] = sum_k softmax_k(feats[n,k]·w) * feats[n,k],
// feats[n,k] = embed_table[neigh_idx[n,k]].
// table [VOCAB,128] f32, attn_w [128] f32, neigh_idx [N,10] (int32 or int64), out [N,128] f32.
//
// R9 = R6 (warp-per-node, online softmax, 2 groups of 5, single launch)
//      + group B rows staged via cp.async.cg into smem, issued BEFORE group A's
//      register gathers: all 10 row loads are in flight at once (R6 had 5),
//      with zero extra register cost and no barriers (each lane waits only on
//      and reads back its own 16B — per-thread cp.async.wait_group suffices).

#define K_NEIGH 10
#define GROUP 5
#define WARPS_PER_BLOCK 8

__global__ __launch_bounds__(256) void attn_agg_kernel(
    const float* __restrict__ table,
    const float* __restrict__ attn_w,
    const int*   __restrict__ idx_words,   // raw index buffer viewed as int32 words
    float* __restrict__ out,
    int n_nodes,
    int vocab)
{
    // Group-B staging: [warp][row][lane], lane-private 16B slots.
    __shared__ float4 stageB[WARPS_PER_BLOCK][GROUP][32];

    int warp = threadIdx.x >> 5;
    int lane = threadIdx.x & 31;
    int node = blockIdx.x * WARPS_PER_BLOCK + warp;
    if (node >= n_nodes) return;

    // Inline dtype detection: int64 indices in [0,2^31) have all-zero odd
    // int32 words; an int32 buffer has random vocab ids there.
    int oddw = 0;
    if (lane < 16) oddw = idx_words[2 * lane + 1];
    bool is32 = __ballot_sync(0xffffffffu, oddw != 0) != 0u;

    // Load this node's K indices (lanes 0..9) -> row byte offsets, shfl-broadcast.
    unsigned mybase = 0;
    if (lane < K_NEIGH) {
        int r;
        if (is32) r = idx_words[node * K_NEIGH + lane];
        else      r = (int)((const long long*)idx_words)[(size_t)node * K_NEIGH + lane];
        r = min(max(r, 0), vocab - 1);
        mybase = (unsigned)r * 512u;
    }

    float4 w4 = ((const float4*)attn_w)[lane];

    // ---- Issue group B (rows 5..9) via cp.async.cg FIRST: no dest registers,
    // bypasses L1, overlaps with everything below. ----
    unsigned sdst0;
    {
        void* p = &stageB[warp][0][lane];
        asm("{ .reg .u64 t; cvta.to.shared.u64 t, %1; cvt.u32.u64 %0, t; }"
            : "=r"(sdst0) : "l"(p));
    }
    #pragma unroll
    for (int k = 0; k < GROUP; k++) {
        unsigned goff = __shfl_sync(0xffffffffu, mybase, GROUP + k) + (unsigned)(lane * 16);
        const void* gsrc = (const char*)table + goff;
        unsigned sdst = sdst0 + (unsigned)(k * 32 * 16);
        asm volatile("cp.async.cg.shared.global [%0], [%1], 16;"
                     :: "r"(sdst), "l"(gsrc));
    }
    asm volatile("cp.async.commit_group;");

    float4 f[GROUP];
    float  s[GROUP];

    // ---- Group A: neighbors 0..4 into registers (5 more loads in flight). ----
    #pragma unroll
    for (int k = 0; k < GROUP; k++) {
        unsigned off = __shfl_sync(0xffffffffu, mybase, k) + (unsigned)(lane * 16);
        f[k] = *(const float4*)((const char*)table + off);
        s[k] = f[k].x * w4.x + f[k].y * w4.y + f[k].z * w4.z + f[k].w * w4.w;
    }
    #pragma unroll
    for (int off = 16; off > 0; off >>= 1) {
        #pragma unroll
        for (int k = 0; k < GROUP; k++)
            s[k] += __shfl_xor_sync(0xffffffffu, s[k], off);
    }
    float m = s[0];
    #pragma unroll
    for (int k = 1; k < GROUP; k++) m = fmaxf(m, s[k]);
    float d = 0.0f;
    float4 acc = make_float4(0.f, 0.f, 0.f, 0.f);
    #pragma unroll
    for (int k = 0; k < GROUP; k++) {
        float e = __expf(s[k] - m);
        d += e;
        acc.x = fmaf(e, f[k].x, acc.x);
        acc.y = fmaf(e, f[k].y, acc.y);
        acc.z = fmaf(e, f[k].z, acc.z);
        acc.w = fmaf(e, f[k].w, acc.w);
    }

    // ---- Group B: wait own copies (per-thread; each lane reads only the 16B
    // it wrote -> no barrier), load from smem into the now-free f[] regs. ----
    asm volatile("cp.async.wait_group 0;");
    #pragma unroll
    for (int k = 0; k < GROUP; k++) {
        f[k] = stageB[warp][k][lane];
        s[k] = f[k].x * w4.x + f[k].y * w4.y + f[k].z * w4.z + f[k].w * w4.w;
    }
    #pragma unroll
    for (int off = 16; off > 0; off >>= 1) {
        #pragma unroll
        for (int k = 0; k < GROUP; k++)
            s[k] += __shfl_xor_sync(0xffffffffu, s[k], off);
    }
    float mB = s[0];
    #pragma unroll
    for (int k = 1; k < GROUP; k++) mB = fmaxf(mB, s[k]);

    // Online-softmax rescale to the combined max.
    float newm  = fmaxf(m, mB);
    float scale = __expf(m - newm);
    d *= scale;
    acc.x *= scale; acc.y *= scale; acc.z *= scale; acc.w *= scale;

    #pragma unroll
    for (int k = 0; k < GROUP; k++) {
        float e = __expf(s[k] - newm);
        d += e;
        acc.x = fmaf(e, f[k].x, acc.x);
        acc.y = fmaf(e, f[k].y, acc.y);
        acc.z = fmaf(e, f[k].z, acc.z);
        acc.w = fmaf(e, f[k].w, acc.w);
    }

    float inv = __frcp_rn(d);
    acc.x *= inv; acc.y *= inv; acc.z *= inv; acc.w *= inv;

    // Streaming store: keep the 51MB output from evicting the table in L2.
    __stcs(&((float4*)out)[(size_t)node * 32 + lane], acc);
}

extern "C" void kernel_launch(void* const* d_in, const int* in_sizes, int n_in,
                              void* d_out, int out_size)
{
    // Identify inputs by element count:
    //   attn_w: exactly 128; table: large multiple of 128; idx: the remaining one.
    int ti = -1, wi = -1, ii = -1;
    for (int i = 0; i < n_in; i++) {
        if (in_sizes[i] == 128 && wi < 0) { wi = i; continue; }
        if (in_sizes[i] >= (1 << 20) && (in_sizes[i] % 128) == 0 && ti < 0) { ti = i; continue; }
    }
    for (int i = 0; i < n_in; i++) if (i != ti && i != wi) { ii = i; break; }

    const float* table  = (const float*)d_in[ti];
    const float* attn_w = (const float*)d_in[wi];
    const int*   nidx   = (const int*)d_in[ii];

    int n_nodes = in_sizes[ii] / K_NEIGH;
    int vocab   = in_sizes[ti] / 128;

    int blocks = (n_nodes + WARPS_PER_BLOCK - 1) / WARPS_PER_BLOCK;
    attn_agg_kernel<<<blocks, 256>>>(table, attn_w, nidx, (float*)d_out,
                                     n_nodes, vocab);
}

// round 11
// speedup vs baseline: 1.4039x; 1.1962x over previous
#include <cuda_runtime.h>

// AttentionAggregator: out[n] = sum_k softmax_k(feats[n,k]·w) * feats[n,k],
// feats[n,k] = embed_table[neigh_idx[n,k]].
// table [VOCAB,128] f32, attn_w [128] f32, neigh_idx [N,10] (int32 or int64), out [N,128] f32.
//
// R10 = R6 (warp-per-node, online softmax in 2 groups of 5, no smem, no
// barriers, single launch) with a PACKED warp reduction: 19 SHFL per 5-score
// group instead of 25 (fold the two 16-lane halves onto different scores
// after the first butterfly round). 50 -> 38 SHFLs per node, relieving the
// 69.6%-busy L1tex/MIO pipe that serves both LDG and SHFL.

#define K_NEIGH 10
#define GROUP 5
#define WARPS_PER_BLOCK 8

// Packed reduction of 5 per-lane partial sums to 5 warp sums, replicated in
// every lane. 19 SHFLs (vs 25 naive). Exact same additions as the butterfly.
__device__ __forceinline__ void reduce5_packed(float s[GROUP], int lane)
{
    // Round 1: full butterfly at offset 16 for all 5 values.
    #pragma unroll
    for (int k = 0; k < GROUP; k++)
        s[k] += __shfl_xor_sync(0xffffffffu, s[k], 16);
    // After xor16, lanes l and l^16 hold identical pairwise sums, so a
    // 16-lane reduction of either half yields the full warp sum.
    bool lo = lane < 16;
    float t0 = lo ? s[0] : s[3];
    float t1 = lo ? s[1] : s[4];
    float t2 = s[2];
    #pragma unroll
    for (int off = 8; off > 0; off >>= 1) {
        t0 += __shfl_xor_sync(0xffffffffu, t0, off);
        t1 += __shfl_xor_sync(0xffffffffu, t1, off);
        t2 += __shfl_xor_sync(0xffffffffu, t2, off);
    }
    // Lower half now holds full sums of s0,s1; upper half of s3,s4; t2 full
    // everywhere. Exchange halves to replicate all 5 in every lane.
    float o0 = __shfl_xor_sync(0xffffffffu, t0, 16);
    float o1 = __shfl_xor_sync(0xffffffffu, t1, 16);
    s[0] = lo ? t0 : o0;
    s[3] = lo ? o0 : t0;
    s[1] = lo ? t1 : o1;
    s[4] = lo ? o1 : t1;
    s[2] = t2;
}

__global__ __launch_bounds__(256) void attn_agg_kernel(
    const float* __restrict__ table,
    const float* __restrict__ attn_w,
    const int*   __restrict__ idx_words,   // raw index buffer viewed as int32 words
    float* __restrict__ out,
    int n_nodes,
    int vocab)
{
    int warp = threadIdx.x >> 5;
    int lane = threadIdx.x & 31;
    int node = blockIdx.x * WARPS_PER_BLOCK + warp;
    if (node >= n_nodes) return;

    // Inline dtype detection: int64 indices in [0,2^31) have all-zero odd
    // int32 words; an int32 buffer has random vocab ids there.
    int oddw = 0;
    if (lane < 16) oddw = idx_words[2 * lane + 1];
    bool is32 = __ballot_sync(0xffffffffu, oddw != 0) != 0u;

    // Load this node's K indices (lanes 0..9) -> row byte offsets.
    unsigned mybase = 0;
    if (lane < K_NEIGH) {
        int r;
        if (is32) r = idx_words[node * K_NEIGH + lane];
        else      r = (int)((const long long*)idx_words)[(size_t)node * K_NEIGH + lane];
        r = min(max(r, 0), vocab - 1);
        mybase = (unsigned)r * 512u;          // 128 floats per row
    }

    float4 w4 = ((const float4*)attn_w)[lane];

    float4 f[GROUP];
    float  s[GROUP];

    // ---- Group A: neighbors 0..4 ----
    #pragma unroll
    for (int k = 0; k < GROUP; k++) {
        unsigned off = __shfl_sync(0xffffffffu, mybase, k) + (unsigned)(lane * 16);
        f[k] = *(const float4*)((const char*)table + off);
        s[k] = f[k].x * w4.x + f[k].y * w4.y + f[k].z * w4.z + f[k].w * w4.w;
    }
    reduce5_packed(s, lane);

    float m = s[0];
    #pragma unroll
    for (int k = 1; k < GROUP; k++) m = fmaxf(m, s[k]);
    float d = 0.0f;
    float4 acc = make_float4(0.f, 0.f, 0.f, 0.f);
    #pragma unroll
    for (int k = 0; k < GROUP; k++) {
        float e = __expf(s[k] - m);
        d += e;
        acc.x = fmaf(e, f[k].x, acc.x);
        acc.y = fmaf(e, f[k].y, acc.y);
        acc.z = fmaf(e, f[k].z, acc.z);
        acc.w = fmaf(e, f[k].w, acc.w);
    }

    // ---- Group B: neighbors 5..9 (reuse f/s registers) ----
    #pragma unroll
    for (int k = 0; k < GROUP; k++) {
        unsigned off = __shfl_sync(0xffffffffu, mybase, GROUP + k) + (unsigned)(lane * 16);
        f[k] = *(const float4*)((const char*)table + off);
        s[k] = f[k].x * w4.x + f[k].y * w4.y + f[k].z * w4.z + f[k].w * w4.w;
    }
    reduce5_packed(s, lane);

    float mB = s[0];
    #pragma unroll
    for (int k = 1; k < GROUP; k++) mB = fmaxf(mB, s[k]);

    // Online-softmax rescale to the combined max.
    float newm  = fmaxf(m, mB);
    float scale = __expf(m - newm);
    d *= scale;
    acc.x *= scale; acc.y *= scale; acc.z *= scale; acc.w *= scale;

    #pragma unroll
    for (int k = 0; k < GROUP; k++) {
        float e = __expf(s[k] - newm);
        d += e;
        acc.x = fmaf(e, f[k].x, acc.x);
        acc.y = fmaf(e, f[k].y, acc.y);
        acc.z = fmaf(e, f[k].z, acc.z);
        acc.w = fmaf(e, f[k].w, acc.w);
    }

    float inv = __frcp_rn(d);
    acc.x *= inv; acc.y *= inv; acc.z *= inv; acc.w *= inv;

    // Streaming store: keep the 51MB output from evicting the table in L2.
    __stcs(&((float4*)out)[(size_t)node * 32 + lane], acc);
}

extern "C" void kernel_launch(void* const* d_in, const int* in_sizes, int n_in,
                              void* d_out, int out_size)
{
    // Identify inputs by element count:
    //   attn_w: exactly 128; table: large multiple of 128; idx: the remaining one.
    int ti = -1, wi = -1, ii = -1;
    for (int i = 0; i < n_in; i++) {
        if (in_sizes[i] == 128 && wi < 0) { wi = i; continue; }
        if (in_sizes[i] >= (1 << 20) && (in_sizes[i] % 128) == 0 && ti < 0) { ti = i; continue; }
    }
    for (int i = 0; i < n_in; i++) if (i != ti && i != wi) { ii = i; break; }

    const float* table  = (const float*)d_in[ti];
    const float* attn_w = (const float*)d_in[wi];
    const int*   nidx   = (const int*)d_in[ii];

    int n_nodes = in_sizes[ii] / K_NEIGH;
    int vocab   = in_sizes[ti] / 128;

    int blocks = (n_nodes + WARPS_PER_BLOCK - 1) / WARPS_PER_BLOCK;
    attn_agg_kernel<<<blocks, 256>>>(table, attn_w, nidx, (float*)d_out,
                                     n_nodes, vocab);
}

// round 12
// speedup vs baseline: 1.4881x; 1.0599x over previous
#include <cuda_runtime.h>

// AttentionAggregator: out[n] = sum_k softmax_k(feats[n,k]·w) * feats[n,k],
// feats[n,k] = embed_table[neigh_idx[n,k]].
// table [VOCAB,128] f32, attn_w [128] f32, neigh_idx [N,10] (int32 or int64), out [N,128] f32.
//
// R11 = R6 body EXACTLY (warp-per-node, online softmax in 2 groups of 5,
// naive butterfly reduction, no smem, no barriers, single launch, __stcs out)
// with 128-thread blocks instead of 256: same 48-warp/SM occupancy (regs=40),
// but half the per-CTA front-batched LDG burst into the L1tex queue and finer
// tail-wave quantization. We are ~94% of the chip LTS ceiling (~569MB @
// ~10.6TB/s); this targets the remaining scheduling/contention residue.

#define K_NEIGH 10
#define GROUP 5
#define WARPS_PER_BLOCK 4
#define BLOCK_THREADS 128

__global__ __launch_bounds__(BLOCK_THREADS) void attn_agg_kernel(
    const float* __restrict__ table,
    const float* __restrict__ attn_w,
    const int*   __restrict__ idx_words,   // raw index buffer viewed as int32 words
    float* __restrict__ out,
    int n_nodes,
    int vocab)
{
    int warp = threadIdx.x >> 5;
    int lane = threadIdx.x & 31;
    int node = blockIdx.x * WARPS_PER_BLOCK + warp;
    if (node >= n_nodes) return;

    // Inline dtype detection: int64 indices in [0,2^31) have all-zero odd
    // int32 words; an int32 buffer has random vocab ids there.
    int oddw = 0;
    if (lane < 16) oddw = idx_words[2 * lane + 1];
    bool is32 = __ballot_sync(0xffffffffu, oddw != 0) != 0u;

    // Load this node's K indices (lanes 0..9) -> row byte offsets.
    unsigned mybase = 0;
    if (lane < K_NEIGH) {
        int r;
        if (is32) r = idx_words[node * K_NEIGH + lane];
        else      r = (int)((const long long*)idx_words)[(size_t)node * K_NEIGH + lane];
        r = min(max(r, 0), vocab - 1);
        mybase = (unsigned)r * 512u;          // 128 floats per row
    }

    float4 w4 = ((const float4*)attn_w)[lane];

    float4 f[GROUP];
    float  s[GROUP];
    float  m, d;
    float4 acc;

    // ---- Group A: neighbors 0..4 ----
    #pragma unroll
    for (int k = 0; k < GROUP; k++) {
        unsigned off = __shfl_sync(0xffffffffu, mybase, k) + (unsigned)(lane * 16);
        f[k] = *(const float4*)((const char*)table + off);
        s[k] = f[k].x * w4.x + f[k].y * w4.y + f[k].z * w4.z + f[k].w * w4.w;
    }
    #pragma unroll
    for (int off = 16; off > 0; off >>= 1) {
        #pragma unroll
        for (int k = 0; k < GROUP; k++)
            s[k] += __shfl_xor_sync(0xffffffffu, s[k], off);
    }
    m = s[0];
    #pragma unroll
    for (int k = 1; k < GROUP; k++) m = fmaxf(m, s[k]);
    d = 0.0f;
    acc = make_float4(0.f, 0.f, 0.f, 0.f);
    #pragma unroll
    for (int k = 0; k < GROUP; k++) {
        float e = __expf(s[k] - m);
        d += e;
        acc.x = fmaf(e, f[k].x, acc.x);
        acc.y = fmaf(e, f[k].y, acc.y);
        acc.z = fmaf(e, f[k].z, acc.z);
        acc.w = fmaf(e, f[k].w, acc.w);
    }

    // ---- Group B: neighbors 5..9 (reuse f/s registers) ----
    #pragma unroll
    for (int k = 0; k < GROUP; k++) {
        unsigned off = __shfl_sync(0xffffffffu, mybase, GROUP + k) + (unsigned)(lane * 16);
        f[k] = *(const float4*)((const char*)table + off);
        s[k] = f[k].x * w4.x + f[k].y * w4.y + f[k].z * w4.z + f[k].w * w4.w;
    }
    #pragma unroll
    for (int off = 16; off > 0; off >>= 1) {
        #pragma unroll
        for (int k = 0; k < GROUP; k++)
            s[k] += __shfl_xor_sync(0xffffffffu, s[k], off);
    }
    float mB = s[0];
    #pragma unroll
    for (int k = 1; k < GROUP; k++) mB = fmaxf(mB, s[k]);

    // Online-softmax rescale to the combined max.
    float newm  = fmaxf(m, mB);
    float scale = __expf(m - newm);
    d *= scale;
    acc.x *= scale; acc.y *= scale; acc.z *= scale; acc.w *= scale;

    #pragma unroll
    for (int k = 0; k < GROUP; k++) {
        float e = __expf(s[k] - newm);
        d += e;
        acc.x = fmaf(e, f[k].x, acc.x);
        acc.y = fmaf(e, f[k].y, acc.y);
        acc.z = fmaf(e, f[k].z, acc.z);
        acc.w = fmaf(e, f[k].w, acc.w);
    }

    float inv = __frcp_rn(d);
    acc.x *= inv; acc.y *= inv; acc.z *= inv; acc.w *= inv;

    // Streaming store: keep the 51MB output from evicting the table in L2.
    __stcs(&((float4*)out)[(size_t)node * 32 + lane], acc);
}

extern "C" void kernel_launch(void* const* d_in, const int* in_sizes, int n_in,
                              void* d_out, int out_size)
{
    // Identify inputs by element count:
    //   attn_w: exactly 128; table: large multiple of 128; idx: the remaining one.
    int ti = -1, wi = -1, ii = -1;
    for (int i = 0; i < n_in; i++) {
        if (in_sizes[i] == 128 && wi < 0) { wi = i; continue; }
        if (in_sizes[i] >= (1 << 20) && (in_sizes[i] % 128) == 0 && ti < 0) { ti = i; continue; }
    }
    for (int i = 0; i < n_in; i++) if (i != ti && i != wi) { ii = i; break; }

    const float* table  = (const float*)d_in[ti];
    const float* attn_w = (const float*)d_in[wi];
    const int*   nidx   = (const int*)d_in[ii];

    int n_nodes = in_sizes[ii] / K_NEIGH;
    int vocab   = in_sizes[ti] / 128;

    int blocks = (n_nodes + WARPS_PER_BLOCK - 1) / WARPS_PER_BLOCK;
    attn_agg_kernel<<<blocks, BLOCK_THREADS>>>(table, attn_w, nidx, (float*)d_out,
                                               n_nodes, vocab);
}

// round 13
// speedup vs baseline: 1.5046x; 1.0111x over previous
#include <cuda_runtime.h>

// AttentionAggregator: out[n] = sum_k softmax_k(feats[n,k]·w) * feats[n,k],
// feats[n,k] = embed_table[neigh_idx[n,k]].
// table [VOCAB,128] f32, attn_w [128] f32, neigh_idx [N,10] (int32 or int64), out [N,128] f32.
//
// R12 = R11 body EXACTLY (warp-per-node, online softmax in 2 groups of 5,
// butterfly reduction, no smem, no barriers, single launch, __stcs out) with
// 64-thread blocks: per-CTA front-batched LDG burst 20 -> 10 (the knob that
// won R11), occupancy 48 -> 50 warps/SM (25 CTAs x 2 warps at regs=40,
// below the 32-CTA/SM cap), finer tail quantization.

#define K_NEIGH 10
#define GROUP 5
#define WARPS_PER_BLOCK 2
#define BLOCK_THREADS 64

__global__ __launch_bounds__(BLOCK_THREADS) void attn_agg_kernel(
    const float* __restrict__ table,
    const float* __restrict__ attn_w,
    const int*   __restrict__ idx_words,   // raw index buffer viewed as int32 words
    float* __restrict__ out,
    int n_nodes,
    int vocab)
{
    int warp = threadIdx.x >> 5;
    int lane = threadIdx.x & 31;
    int node = blockIdx.x * WARPS_PER_BLOCK + warp;
    if (node >= n_nodes) return;

    // Inline dtype detection: int64 indices in [0,2^31) have all-zero odd
    // int32 words; an int32 buffer has random vocab ids there.
    int oddw = 0;
    if (lane < 16) oddw = idx_words[2 * lane + 1];
    bool is32 = __ballot_sync(0xffffffffu, oddw != 0) != 0u;

    // Load this node's K indices (lanes 0..9) -> row byte offsets.
    unsigned mybase = 0;
    if (lane < K_NEIGH) {
        int r;
        if (is32) r = idx_words[node * K_NEIGH + lane];
        else      r = (int)((const long long*)idx_words)[(size_t)node * K_NEIGH + lane];
        r = min(max(r, 0), vocab - 1);
        mybase = (unsigned)r * 512u;          // 128 floats per row
    }

    float4 w4 = ((const float4*)attn_w)[lane];

    float4 f[GROUP];
    float  s[GROUP];
    float  m, d;
    float4 acc;

    // ---- Group A: neighbors 0..4 ----
    #pragma unroll
    for (int k = 0; k < GROUP; k++) {
        unsigned off = __shfl_sync(0xffffffffu, mybase, k) + (unsigned)(lane * 16);
        f[k] = *(const float4*)((const char*)table + off);
        s[k] = f[k].x * w4.x + f[k].y * w4.y + f[k].z * w4.z + f[k].w * w4.w;
    }
    #pragma unroll
    for (int off = 16; off > 0; off >>= 1) {
        #pragma unroll
        for (int k = 0; k < GROUP; k++)
            s[k] += __shfl_xor_sync(0xffffffffu, s[k], off);
    }
    m = s[0];
    #pragma unroll
    for (int k = 1; k < GROUP; k++) m = fmaxf(m, s[k]);
    d = 0.0f;
    acc = make_float4(0.f, 0.f, 0.f, 0.f);
    #pragma unroll
    for (int k = 0; k < GROUP; k++) {
        float e = __expf(s[k] - m);
        d += e;
        acc.x = fmaf(e, f[k].x, acc.x);
        acc.y = fmaf(e, f[k].y, acc.y);
        acc.z = fmaf(e, f[k].z, acc.z);
        acc.w = fmaf(e, f[k].w, acc.w);
    }

    // ---- Group B: neighbors 5..9 (reuse f/s registers) ----
    #pragma unroll
    for (int k = 0; k < GROUP; k++) {
        unsigned off = __shfl_sync(0xffffffffu, mybase, GROUP + k) + (unsigned)(lane * 16);
        f[k] = *(const float4*)((const char*)table + off);
        s[k] = f[k].x * w4.x + f[k].y * w4.y + f[k].z * w4.z + f[k].w * w4.w;
    }
    #pragma unroll
    for (int off = 16; off > 0; off >>= 1) {
        #pragma unroll
        for (int k = 0; k < GROUP; k++)
            s[k] += __shfl_xor_sync(0xffffffffu, s[k], off);
    }
    float mB = s[0];
    #pragma unroll
    for (int k = 1; k < GROUP; k++) mB = fmaxf(mB, s[k]);

    // Online-softmax rescale to the combined max.
    float newm  = fmaxf(m, mB);
    float scale = __expf(m - newm);
    d *= scale;
    acc.x *= scale; acc.y *= scale; acc.z *= scale; acc.w *= scale;

    #pragma unroll
    for (int k = 0; k < GROUP; k++) {
        float e = __expf(s[k] - newm);
        d += e;
        acc.x = fmaf(e, f[k].x, acc.x);
        acc.y = fmaf(e, f[k].y, acc.y);
        acc.z = fmaf(e, f[k].z, acc.z);
        acc.w = fmaf(e, f[k].w, acc.w);
    }

    float inv = __frcp_rn(d);
    acc.x *= inv; acc.y *= inv; acc.z *= inv; acc.w *= inv;

    // Streaming store: keep the 51MB output from evicting the table in L2.
    __stcs(&((float4*)out)[(size_t)node * 32 + lane], acc);
}

extern "C" void kernel_launch(void* const* d_in, const int* in_sizes, int n_in,
                              void* d_out, int out_size)
{
    // Identify inputs by element count:
    //   attn_w: exactly 128; table: large multiple of 128; idx: the remaining one.
    int ti = -1, wi = -1, ii = -1;
    for (int i = 0; i < n_in; i++) {
        if (in_sizes[i] == 128 && wi < 0) { wi = i; continue; }
        if (in_sizes[i] >= (1 << 20) && (in_sizes[i] % 128) == 0 && ti < 0) { ti = i; continue; }
    }
    for (int i = 0; i < n_in; i++) if (i != ti && i != wi) { ii = i; break; }

    const float* table  = (const float*)d_in[ti];
    const float* attn_w = (const float*)d_in[wi];
    const int*   nidx   = (const int*)d_in[ii];

    int n_nodes = in_sizes[ii] / K_NEIGH;
    int vocab   = in_sizes[ti] / 128;

    int blocks = (n_nodes + WARPS_PER_BLOCK - 1) / WARPS_PER_BLOCK;
    attn_agg_kernel<<<blocks, BLOCK_THREADS>>>(table, attn_w, nidx, (float*)d_out,
                                               n_nodes, vocab);
}